// round 12
// baseline (speedup 1.0000x reference)
#include <cuda_runtime.h>
#include <cstdint>

#define NH      16
#define NSPLIT  28            // 28*16 = 448 CTAs ~ one wave at occ 3 on 152 SMs
#define CHUNK   586           // ceil(16384/28)
#define KS      64            // samples per panel (two 32-sample phases)
#define PH      32
#define NSAMP   16384
#define DECAYF  0.95f

// Deterministic split-K partials: [split][h][64][64] ~7.3MB
__device__ float g_partial[NSPLIT * NH * 4096];

__device__ __forceinline__ uint32_t smem_u32(const void* p) {
    uint32_t a;
    asm("{ .reg .u64 t; cvta.to.shared.u64 t, %1; cvt.u32.u64 %0, t; }"
        : "=r"(a) : "l"(p));
    return a;
}

#define LDSM_X4_T(r, addr)                                                     \
    asm volatile("ldmatrix.sync.aligned.m8n8.x4.trans.shared.b16 "             \
                 "{%0,%1,%2,%3}, [%4];"                                        \
                 : "=r"((r)[0]), "=r"((r)[1]), "=r"((r)[2]), "=r"((r)[3])      \
                 : "r"(addr))

__device__ __forceinline__ void mma16816(float* c, const uint32_t* a,
                                         uint32_t b0, uint32_t b1)
{
    asm volatile(
        "mma.sync.aligned.m16n8k16.row.col.f32.bf16.bf16.f32 "
        "{%0,%1,%2,%3}, {%4,%5,%6,%7}, {%8,%9}, {%0,%1,%2,%3};"
        : "+f"(c[0]), "+f"(c[1]), "+f"(c[2]), "+f"(c[3])
        : "r"(a[0]), "r"(a[1]), "r"(a[2]), "r"(a[3]), "r"(b0), "r"(b1));
}

// hi/lo bf16 split of 8 fp32 values -> two uint4 (memory order x0..x7)
__device__ __forceinline__ void split8(const float* x, uint4& hi, uint4& lo)
{
    uint32_t h[4], q[4];
#pragma unroll
    for (int i = 0; i < 4; ++i)
        asm("cvt.rn.bf16x2.f32 %0, %1, %2;" : "=r"(h[i])
            : "f"(x[2 * i + 1]), "f"(x[2 * i]));
#pragma unroll
    for (int i = 0; i < 4; ++i) {
        float g0 = __uint_as_float(h[i] << 16);
        float g1 = __uint_as_float(h[i] & 0xFFFF0000u);
        asm("cvt.rn.bf16x2.f32 %0, %1, %2;" : "=r"(q[i])
            : "f"(x[2 * i + 1] - g1), "f"(x[2 * i] - g0));
    }
    hi = make_uint4(h[0], h[1], h[2], h[3]);
    lo = make_uint4(q[0], q[1], q[2], q[3]);
}

// smem (32 KB): KSH @ 0, KSL @ 8192, VSH @ 16384, VSL @ 24576
// tile = [64 s][64 dim] bf16, 128B/row, XOR swizzle: off ^ ((s&7)<<4)

__global__ __launch_bounds__(256, 3)
void l1writer_mma_kernel(const float* __restrict__ keys,
                         const float* __restrict__ values,
                         const float* __restrict__ rho)
{
    __shared__ __align__(128) char buf[32768];
    const int tid  = threadIdx.x, lane = tid & 31, wid = tid >> 5;
    const int split = blockIdx.x, h = blockIdx.y;
    const int n0   = split * CHUNK;
    const int nend = min(n0 + CHUNK, NSAMP);
    const int npanel = (nend - n0 + KS - 1) / KS;
    const uint32_t sb = smem_u32(buf);

    // Loader mapping: thread = (sample s0 = tid>>3, dim-octet o = tid&7)
    const int s0 = tid >> 3, oct = tid & 7;
    const uint32_t st_off = 0; // per-phase row offset added below

    // Warp tile: 4 warps along M (dk), 2 along N (dv); each warp 16x32
    const int m0  = (wid >> 1) * 16;
    const int nn0 = (wid & 1) * 32;

    // Per-lane LDSM addresses, k16-step advance = +2048B
    const int half = lane >> 3, l7 = lane & 7;
    const int a_s = l7 + ((half >> 1) << 3);
    const int a_m = m0 + ((half & 1) << 3);
    const uint32_t aoff = (uint32_t)(a_s * 128 + a_m * 2) ^ ((a_s & 7) << 4);
    const int b_s = l7 + ((half & 1) << 3);
    const int b_n = nn0 + ((half >> 1) << 3);
    const uint32_t boff0 = (uint32_t)(b_s * 128 + b_n * 2) ^ ((b_s & 7) << 4);
    const uint32_t boff1 = (uint32_t)(b_s * 128 + (b_n + 16) * 2) ^ ((b_s & 7) << 4);

    const uint32_t aAh  = sb + aoff;
    const uint32_t aAl  = sb + 8192  + aoff;
    const uint32_t aBh0 = sb + 16384 + boff0;
    const uint32_t aBh1 = sb + 16384 + boff1;
    const uint32_t aBl0 = sb + 24576 + boff0;
    const uint32_t aBl1 = sb + 24576 + boff1;

    float c[4][4];
#pragma unroll
    for (int t = 0; t < 4; ++t)
#pragma unroll
        for (int i = 0; i < 4; ++i) c[t][i] = 0.f;

    // Loader regs: kv[0..1]=K octet pair, kv[2..3]=V octet pair, rr=rho
    float4 kv[4];
    float  rr;

#define LOAD_PHASE(P, PHI)                                                     \
    do {                                                                       \
        int n = n0 + (P) * KS + (PHI) * PH + s0;                               \
        if (n < nend) {                                                        \
            const float* kp = keys   + (size_t)n * (NH * 64) + h * 64 + oct * 8; \
            const float* vp = values + (size_t)n * (NH * 64) + h * 64 + oct * 8; \
            kv[0] = *(const float4*)kp;                                        \
            kv[1] = *(const float4*)(kp + 4);                                  \
            kv[2] = *(const float4*)vp;                                        \
            kv[3] = *(const float4*)(vp + 4);                                  \
            rr    = __ldg(rho + n);                                            \
        } else {                                                               \
            kv[0] = kv[1] = kv[2] = kv[3] = make_float4(0.f, 0.f, 0.f, 0.f);   \
            rr = 0.f;                                                          \
        }                                                                      \
    } while (0)

#define STORE_PHASE(PHI)                                                       \
    do {                                                                       \
        int srow = (PHI) * PH + s0;                                            \
        uint32_t off = (uint32_t)(srow * 128 + oct * 16) ^ ((srow & 7) << 4);  \
        float xk[8] = { kv[0].x * rr, kv[0].y * rr, kv[0].z * rr, kv[0].w * rr,\
                        kv[1].x * rr, kv[1].y * rr, kv[1].z * rr, kv[1].w * rr };\
        uint4 khi, klo;                                                        \
        split8(xk, khi, klo);                                                  \
        *(uint4*)(buf + off)         = khi;                                    \
        *(uint4*)(buf + 8192 + off)  = klo;                                    \
        float xv[8] = { kv[2].x, kv[2].y, kv[2].z, kv[2].w,                    \
                        kv[3].x, kv[3].y, kv[3].z, kv[3].w };                  \
        uint4 vhi, vlo;                                                        \
        split8(xv, vhi, vlo);                                                  \
        *(uint4*)(buf + 16384 + off) = vhi;                                    \
        *(uint4*)(buf + 24576 + off) = vlo;                                    \
    } while (0)

    // Prologue: phase 0 of panel 0
    LOAD_PHASE(0, 0);

    for (int p = 0; p < npanel; ++p) {
        __syncthreads();        // previous panel's compute done
        STORE_PHASE(0);         // commit phase 0 (regs -> smem)
        LOAD_PHASE(p, 1);       // phase 1 loads (overlap with phase-0 stores)
        STORE_PHASE(1);
        __syncthreads();

        if (p + 1 < npanel) LOAD_PHASE(p + 1, 0);   // prefetch next panel

        // Compute: 4 k16-steps, 6 LDSM.x4 + 12 HMMA each
#pragma unroll
        for (int st = 0; st < 4; ++st) {
            const uint32_t adv = st * 2048;
            uint32_t ah[4], al[4], bh[4], bh2[4], bl[4], bl2[4];
            LDSM_X4_T(ah,  aAh  + adv);
            LDSM_X4_T(bh,  aBh0 + adv);
            LDSM_X4_T(bh2, aBh1 + adv);
            LDSM_X4_T(al,  aAl  + adv);
            LDSM_X4_T(bl,  aBl0 + adv);
            LDSM_X4_T(bl2, aBl1 + adv);
            // Ah*Bh
            mma16816(c[0], ah, bh[0],  bh[1]);
            mma16816(c[1], ah, bh[2],  bh[3]);
            mma16816(c[2], ah, bh2[0], bh2[1]);
            mma16816(c[3], ah, bh2[2], bh2[3]);
            // Ah*Bl
            mma16816(c[0], ah, bl[0],  bl[1]);
            mma16816(c[1], ah, bl[2],  bl[3]);
            mma16816(c[2], ah, bl2[0], bl2[1]);
            mma16816(c[3], ah, bl2[2], bl2[3]);
            // Al*Bh
            mma16816(c[0], al, bh[0],  bh[1]);
            mma16816(c[1], al, bh[2],  bh[3]);
            mma16816(c[2], al, bh2[0], bh2[1]);
            mma16816(c[3], al, bh2[2], bh2[3]);
        }
    }

    // Write deterministic partial tile
    const int gid = lane >> 2, tig = lane & 3;
    float* base = g_partial + ((size_t)split * NH + h) * 4096;
#pragma unroll
    for (int t = 0; t < 4; ++t) {
        int nc = nn0 + t * 8 + 2 * tig;
        *(float2*)(base + (m0 + gid)     * 64 + nc) = make_float2(c[t][0], c[t][1]);
        *(float2*)(base + (m0 + gid + 8) * 64 + nc) = make_float2(c[t][2], c[t][3]);
    }
}

// out[i] = 0.95*memory[i] + sum_s partial[s][i]
__global__ __launch_bounds__(128)
void l1writer_reduce_kernel(const float* __restrict__ memory,
                            float* __restrict__ out)
{
    int i = blockIdx.x * 128 + threadIdx.x;   // 0..65535
    float acc = DECAYF * memory[i];
#pragma unroll
    for (int s = 0; s < NSPLIT; ++s)
        acc += g_partial[(size_t)s * (NH * 4096) + i];
    out[i] = acc;
}

extern "C" void kernel_launch(void* const* d_in, const int* in_sizes, int n_in,
                              void* d_out, int out_size)
{
    const float* memory = (const float*)d_in[0];  // (16,64,64)
    const float* keys   = (const float*)d_in[1];  // (4,4096,16,64)
    const float* values = (const float*)d_in[2];  // (4,4096,16,64)
    const float* rho    = (const float*)d_in[3];  // (4,4096)
    float* out = (float*)d_out;

    dim3 grid(NSPLIT, NH);
    l1writer_mma_kernel<<<grid, 256>>>(keys, values, rho);
    l1writer_reduce_kernel<<<(NH * 4096) / 128, 128>>>(memory, out);
}

// round 13
// speedup vs baseline: 1.0589x; 1.0589x over previous
#include <cuda_runtime.h>
#include <cstdint>

#define NH      16
#define NSPLIT  28            // 28*16 = 448 CTAs ~ one wave at occ 3 on 152 SMs
#define CHUNK   586           // ceil(16384/28)
#define KS      32            // samples per panel
#define NSAMP   16384
#define DECAYF  0.95f

// Deterministic split-K partials: [split][h][64][64] ~7.3MB
__device__ float g_partial[NSPLIT * NH * 4096];

__device__ __forceinline__ uint32_t smem_u32(const void* p) {
    uint32_t a;
    asm("{ .reg .u64 t; cvta.to.shared.u64 t, %1; cvt.u32.u64 %0, t; }"
        : "=r"(a) : "l"(p));
    return a;
}

#define LDSM_X4_T(r, addr)                                                     \
    asm volatile("ldmatrix.sync.aligned.m8n8.x4.trans.shared.b16 "             \
                 "{%0,%1,%2,%3}, [%4];"                                        \
                 : "=r"((r)[0]), "=r"((r)[1]), "=r"((r)[2]), "=r"((r)[3])      \
                 : "r"(addr))

__device__ __forceinline__ void mma16816(float* c, const uint32_t* a,
                                         uint32_t b0, uint32_t b1)
{
    asm volatile(
        "mma.sync.aligned.m16n8k16.row.col.f32.bf16.bf16.f32 "
        "{%0,%1,%2,%3}, {%4,%5,%6,%7}, {%8,%9}, {%0,%1,%2,%3};"
        : "+f"(c[0]), "+f"(c[1]), "+f"(c[2]), "+f"(c[3])
        : "r"(a[0]), "r"(a[1]), "r"(a[2]), "r"(a[3]), "r"(b0), "r"(b1));
}

// hi/lo bf16 split of 8 fp32 values -> two uint4 (memory order x0..x7)
__device__ __forceinline__ void split8(const float* x, uint4& hi, uint4& lo)
{
    uint32_t h[4], q[4];
#pragma unroll
    for (int i = 0; i < 4; ++i)
        asm("cvt.rn.bf16x2.f32 %0, %1, %2;" : "=r"(h[i])
            : "f"(x[2 * i + 1]), "f"(x[2 * i]));
#pragma unroll
    for (int i = 0; i < 4; ++i) {
        float g0 = __uint_as_float(h[i] << 16);
        float g1 = __uint_as_float(h[i] & 0xFFFF0000u);
        asm("cvt.rn.bf16x2.f32 %0, %1, %2;" : "=r"(q[i])
            : "f"(x[2 * i + 1] - g1), "f"(x[2 * i] - g0));
    }
    hi = make_uint4(h[0], h[1], h[2], h[3]);
    lo = make_uint4(q[0], q[1], q[2], q[3]);
}

// smem tile map (16 KB): KSH @ 0, KSL @ 4096, VSH @ 8192, VSL @ 12288
// tile = [32 s][64 dim] bf16, 128B/row, XOR swizzle: off ^ ((s&7)<<4)

__global__ __launch_bounds__(256, 3)
void l1writer_mma_kernel(const float* __restrict__ keys,
                         const float* __restrict__ values,
                         const float* __restrict__ rho)
{
    __shared__ __align__(128) char buf[16384];
    const int tid  = threadIdx.x, lane = tid & 31, wid = tid >> 5;
    const int split = blockIdx.x, h = blockIdx.y;
    const int n0   = split * CHUNK;
    const int nend = min(n0 + CHUNK, NSAMP);
    const int npanel = (nend - n0 + KS - 1) / KS;

    // Loader mapping: thread = (sample s0 = tid>>3, dim-octet oct = tid&7)
    const int s0 = tid >> 3, oct = tid & 7;
    const uint32_t soff = (uint32_t)(s0 * 128 + oct * 16) ^ ((s0 & 7) << 4);

    // Warp tile: 4 warps along M (dk), 2 along N (dv); each warp 16x32
    const int m0  = (wid >> 1) * 16;
    const int nn0 = (wid & 1) * 32;

    const uint32_t sb = smem_u32(buf);
    // Per-lane LDSM addresses (logical -> swizzled), k16-step advance = +2048B
    const int half = lane >> 3, l7 = lane & 7;
    const int a_s = l7 + ((half >> 1) << 3);
    const int a_m = m0 + ((half & 1) << 3);
    const uint32_t aoff = (uint32_t)(a_s * 128 + a_m * 2) ^ ((a_s & 7) << 4);
    const int b_s = l7 + ((half & 1) << 3);
    const int b_n = nn0 + ((half >> 1) << 3);
    const uint32_t boff0 = (uint32_t)(b_s * 128 + b_n * 2) ^ ((b_s & 7) << 4);
    const uint32_t boff1 = (uint32_t)(b_s * 128 + (b_n + 16) * 2) ^ ((b_s & 7) << 4);

    const uint32_t aAh  = sb + aoff;
    const uint32_t aAl  = sb + 4096  + aoff;
    const uint32_t aBh0 = sb + 8192  + boff0;
    const uint32_t aBh1 = sb + 8192  + boff1;
    const uint32_t aBl0 = sb + 12288 + boff0;
    const uint32_t aBl1 = sb + 12288 + boff1;

    float c[4][4];
#pragma unroll
    for (int t = 0; t < 4; ++t)
#pragma unroll
        for (int i = 0; i < 4; ++i) c[t][i] = 0.f;

    // Loader regs: one sample per thread (2 float4 K, 2 float4 V, 1 rho)
    float4 kv[4];
    float  rr;

#define LOAD_PANEL(P)                                                          \
    do {                                                                       \
        int n = n0 + (P) * KS + s0;                                            \
        if (n < nend) {                                                        \
            const float* kp = keys   + (size_t)n * (NH * 64) + h * 64 + oct * 8; \
            const float* vp = values + (size_t)n * (NH * 64) + h * 64 + oct * 8; \
            kv[0] = *(const float4*)kp;                                        \
            kv[1] = *(const float4*)(kp + 4);                                  \
            kv[2] = *(const float4*)vp;                                        \
            kv[3] = *(const float4*)(vp + 4);                                  \
            rr    = __ldg(rho + n);                                            \
        } else {                                                               \
            kv[0] = kv[1] = kv[2] = kv[3] = make_float4(0.f, 0.f, 0.f, 0.f);   \
            rr = 0.f;                                                          \
        }                                                                      \
    } while (0)

#define STORE_PANEL()                                                          \
    do {                                                                       \
        float xk[8] = { kv[0].x * rr, kv[0].y * rr, kv[0].z * rr, kv[0].w * rr,\
                        kv[1].x * rr, kv[1].y * rr, kv[1].z * rr, kv[1].w * rr };\
        uint4 khi, klo;                                                        \
        split8(xk, khi, klo);                                                  \
        *(uint4*)(buf + soff)         = khi;                                   \
        *(uint4*)(buf + 4096 + soff)  = klo;                                   \
        float xv[8] = { kv[2].x, kv[2].y, kv[2].z, kv[2].w,                    \
                        kv[3].x, kv[3].y, kv[3].z, kv[3].w };                  \
        uint4 vhi, vlo;                                                        \
        split8(xv, vhi, vlo);                                                  \
        *(uint4*)(buf + 8192 + soff)  = vhi;                                   \
        *(uint4*)(buf + 12288 + soff) = vlo;                                   \
    } while (0)

    // Prologue: prefetch panel 0
    LOAD_PANEL(0);

    for (int p = 0; p < npanel; ++p) {
        __syncthreads();   // previous panel's compute done before overwrite
        STORE_PANEL();     // commit prefetched regs -> smem
        __syncthreads();

        if (p + 1 < npanel) LOAD_PANEL(p + 1);   // hidden under compute below

        // Compute: 2 k16-steps, 6 LDSM.x4 + 12 HMMA each
#pragma unroll
        for (int st = 0; st < 2; ++st) {
            const uint32_t adv = st * 2048;
            uint32_t ah[4], al[4], bh[4], bh2[4], bl[4], bl2[4];
            LDSM_X4_T(ah,  aAh  + adv);
            LDSM_X4_T(bh,  aBh0 + adv);
            LDSM_X4_T(bh2, aBh1 + adv);
            LDSM_X4_T(al,  aAl  + adv);
            LDSM_X4_T(bl,  aBl0 + adv);
            LDSM_X4_T(bl2, aBl1 + adv);
            // Ah*Bh
            mma16816(c[0], ah, bh[0],  bh[1]);
            mma16816(c[1], ah, bh[2],  bh[3]);
            mma16816(c[2], ah, bh2[0], bh2[1]);
            mma16816(c[3], ah, bh2[2], bh2[3]);
            // Ah*Bl
            mma16816(c[0], ah, bl[0],  bl[1]);
            mma16816(c[1], ah, bl[2],  bl[3]);
            mma16816(c[2], ah, bl2[0], bl2[1]);
            mma16816(c[3], ah, bl2[2], bl2[3]);
            // Al*Bh
            mma16816(c[0], al, bh[0],  bh[1]);
            mma16816(c[1], al, bh[2],  bh[3]);
            mma16816(c[2], al, bh2[0], bh2[1]);
            mma16816(c[3], al, bh2[2], bh2[3]);
        }
    }

    // Write deterministic partial tile
    const int gid = lane >> 2, tig = lane & 3;
    float* base = g_partial + ((size_t)split * NH + h) * 4096;
#pragma unroll
    for (int t = 0; t < 4; ++t) {
        int nc = nn0 + t * 8 + 2 * tig;
        *(float2*)(base + (m0 + gid)     * 64 + nc) = make_float2(c[t][0], c[t][1]);
        *(float2*)(base + (m0 + gid + 8) * 64 + nc) = make_float2(c[t][2], c[t][3]);
    }
}

// out[i] = 0.95*memory[i] + sum_s partial[s][i]
__global__ __launch_bounds__(256)
void l1writer_reduce_kernel(const float* __restrict__ memory,
                            float* __restrict__ out)
{
    int i = blockIdx.x * 256 + threadIdx.x;   // 0..65535
    float acc = DECAYF * memory[i];
#pragma unroll
    for (int s = 0; s < NSPLIT; ++s)
        acc += g_partial[(size_t)s * (NH * 4096) + i];
    out[i] = acc;
}

extern "C" void kernel_launch(void* const* d_in, const int* in_sizes, int n_in,
                              void* d_out, int out_size)
{
    const float* memory = (const float*)d_in[0];  // (16,64,64)
    const float* keys   = (const float*)d_in[1];  // (4,4096,16,64)
    const float* values = (const float*)d_in[2];  // (4,4096,16,64)
    const float* rho    = (const float*)d_in[3];  // (4,4096)
    float* out = (float*)d_out;

    dim3 grid(NSPLIT, NH);
    l1writer_mma_kernel<<<grid, 256>>>(keys, values, rho);
    l1writer_reduce_kernel<<<(NH * 4096) / 256, 256>>>(memory, out);
}